// round 10
// baseline (speedup 1.0000x reference)
#include <cuda_runtime.h>
#include <math.h>
#include <stdint.h>

#define B_  32
#define S_  512
#define D_  768
#define H_  8
#define DK_ 96
#define C_  3
#define QKW 1536   // fused q|k width

// ---------------- scratch (device globals; no allocs allowed) ----------------
__device__ float g_qk    [(long)B_*S_*QKW];
__device__ float g_wqk   [D_*QKW];              // TRANSB layout [1536][768]
__device__ float g_scores[(long)B_*H_*S_*S_];   // 256 MiB
__device__ float g_adj   [(long)B_*S_*S_];
__device__ float g_den   [B_*S_];
__device__ float g_vt    [B_*S_*D_];            // v/u transposed [b][768][512]
__device__ float g_t1    [B_*S_*D_];
__device__ float g_t2    [B_*S_*D_];
__device__ float g_pool  [B_*D_];
__device__ float g_hid   [B_*D_];

// ---------------- bf16x3 helpers ----------------
__device__ __forceinline__ void bsplit2(float x, float y, uint32_t& h, uint32_t& l) {
    uint32_t bx = __float_as_uint(x), by = __float_as_uint(y);
    h = __byte_perm(bx, by, 0x7632);          // {y_hi16, x_hi16}
    float lx = x - __uint_as_float(bx & 0xFFFF0000u);
    float ly = y - __uint_as_float(by & 0xFFFF0000u);
    asm("cvt.rn.bf16x2.f32 %0, %1, %2;" : "=r"(l) : "f"(ly), "f"(lx));
}
__device__ __forceinline__ void mma_bf16(float* c, const uint32_t* a, const uint32_t* b) {
    asm volatile(
        "mma.sync.aligned.m16n8k16.row.col.f32.bf16.bf16.f32 "
        "{%0,%1,%2,%3}, {%4,%5,%6,%7}, {%8,%9}, {%0,%1,%2,%3};"
        : "+f"(c[0]), "+f"(c[1]), "+f"(c[2]), "+f"(c[3])
        : "r"(a[0]), "r"(a[1]), "r"(a[2]), "r"(a[3]), "r"(b[0]), "r"(b[1]));
}

// ---------------- fast exp ----------------
__device__ __forceinline__ float fast_exp(float x) {
    float y = fmaxf(x * 1.4426950408889634f, -126.0f);
    float t = __fadd_rn(y, 12582912.0f);
    float n = __fsub_rn(t, 12582912.0f);
    float f = __fsub_rn(y, n);
    float p = 0.0013333558f;
    p = fmaf(p, f, 0.0096181291f);
    p = fmaf(p, f, 0.0555041087f);
    p = fmaf(p, f, 0.2402265070f);
    p = fmaf(p, f, 0.6931471806f);
    p = fmaf(p, f, 1.0f);
    int e = (int)n;
    return __int_as_float(__float_as_int(p) + (e << 23));
}

// ---------------- weight concat/transpose -> TRANSB layout [1536][768] ------
__global__ void wqk_transpose(const float* __restrict__ wq,
                              const float* __restrict__ wk,
                              float* __restrict__ out)
{
    int idx = blockIdx.x * 256 + threadIdx.x;
    if (idx >= H_ * D_ * DK_) return;
    int h = idx / (D_ * DK_);
    int r = idx % (D_ * DK_);
    int d = r / DK_, j = r % DK_;
    out[(long)(h * DK_ + j) * D_ + d]        = wq[idx];
    out[(long)(D_ + h * DK_ + j) * D_ + d]   = wk[idx];
}

// ========= bf16x3 GEMM: 128x128 tile, 4 warps of 64x64, KC=16 ===============
// B ALWAYS [N,K] rows (TRANSB). Two-level batch z = zb*hdiv + zh.
// TROUT (no bias/relu/denom): write C transposed via smem for coalescing:
//   addr = ((row>>9)*N + col)*512 + (row&511)
#define SRW 12
#define TSZ (128 * SRW)
#define MMA_SMEM (8 * TSZ * 4)          // 49152 B

template<bool TROUT, bool BIAS, bool RELU, bool DENOM>
__global__ __launch_bounds__(128, 2) void gemm_mma(
    const float* __restrict__ A, const float* __restrict__ Bm, float* __restrict__ C,
    int M, int N, int K, int lda, int ldb,
    long sA, long hA, long sB, long hB, long sC, int hdiv,
    const float* __restrict__ bias, const float* __restrict__ denom, int dstride)
{
    extern __shared__ uint32_t sm[];

    const int tid  = threadIdx.x;
    const int wid  = tid >> 5;
    const int lane = tid & 31;
    const int g    = lane >> 2;
    const int t    = lane & 3;
    const int wr   = wid & 1;
    const int wc   = wid >> 1;

    const int z  = blockIdx.z;
    const int zb = z / hdiv;
    const int zh = z - zb * hdiv;
    A  += (long)zb * sA + (long)zh * hA;
    Bm += (long)zb * sB + (long)zh * hB;
    C  += (long)z * sC;

    const int m0 = blockIdx.y * 128;
    const int n0 = blockIdx.x * 128;

    float acc[4][8][4];
#pragma unroll
    for (int i = 0; i < 4; i++)
#pragma unroll
        for (int j = 0; j < 8; j++)
#pragma unroll
            for (int e = 0; e < 4; e++) acc[i][j][e] = 0.0f;

    float4 pa[4], pb[4];

    auto ldgf = [&](int c) {
        const float* ap = A + (long)(m0 + tid) * lda + c * 16;
#pragma unroll
        for (int i = 0; i < 4; i++) pa[i] = *(const float4*)(ap + i * 4);
        const float* bp = Bm + (long)(n0 + tid) * ldb + c * 16;
#pragma unroll
        for (int i = 0; i < 4; i++) pb[i] = *(const float4*)(bp + i * 4);
    };
    auto stsf = [&](int s) {
        uint32_t hw[8], lw[8];
#pragma unroll
        for (int i = 0; i < 4; i++) {
            bsplit2(pa[i].x, pa[i].y, hw[2*i],   lw[2*i]);
            bsplit2(pa[i].z, pa[i].w, hw[2*i+1], lw[2*i+1]);
        }
        uint32_t* dah = sm + s * TSZ + tid * SRW;
        uint32_t* dal = sm + (2 + s) * TSZ + tid * SRW;
        *(uint4*)(dah)     = make_uint4(hw[0], hw[1], hw[2], hw[3]);
        *(uint4*)(dah + 4) = make_uint4(hw[4], hw[5], hw[6], hw[7]);
        *(uint4*)(dal)     = make_uint4(lw[0], lw[1], lw[2], lw[3]);
        *(uint4*)(dal + 4) = make_uint4(lw[4], lw[5], lw[6], lw[7]);
#pragma unroll
        for (int i = 0; i < 4; i++) {
            bsplit2(pb[i].x, pb[i].y, hw[2*i],   lw[2*i]);
            bsplit2(pb[i].z, pb[i].w, hw[2*i+1], lw[2*i+1]);
        }
        uint32_t* dbh = sm + (4 + s) * TSZ + tid * SRW;
        uint32_t* dbl = sm + (6 + s) * TSZ + tid * SRW;
        *(uint4*)(dbh)     = make_uint4(hw[0], hw[1], hw[2], hw[3]);
        *(uint4*)(dbh + 4) = make_uint4(hw[4], hw[5], hw[6], hw[7]);
        *(uint4*)(dbl)     = make_uint4(lw[0], lw[1], lw[2], lw[3]);
        *(uint4*)(dbl + 4) = make_uint4(lw[4], lw[5], lw[6], lw[7]);
    };

    auto compute = [&](int s) {
        const uint32_t* aH = sm + s * TSZ;
        const uint32_t* aL = sm + (2 + s) * TSZ;
        const uint32_t* bH = sm + (4 + s) * TSZ;
        const uint32_t* bL = sm + (6 + s) * TSZ;
        uint32_t ah[4][4], al[4][4];
#pragma unroll
        for (int mt = 0; mt < 4; mt++) {
            const int base = (wr * 64 + mt * 16 + g) * SRW + t;
            ah[mt][0] = aH[base];
            ah[mt][1] = aH[base + 8 * SRW];
            ah[mt][2] = aH[base + 4];
            ah[mt][3] = aH[base + 8 * SRW + 4];
            al[mt][0] = aL[base];
            al[mt][1] = aL[base + 8 * SRW];
            al[mt][2] = aL[base + 4];
            al[mt][3] = aL[base + 8 * SRW + 4];
        }
#pragma unroll
        for (int nt = 0; nt < 8; nt++) {
            const int nb = (wc * 64 + nt * 8 + g) * SRW + t;
            uint32_t bh[2], bl[2];
            bh[0] = bH[nb];
            bh[1] = bH[nb + 4];
            bl[0] = bL[nb];
            bl[1] = bL[nb + 4];
#pragma unroll
            for (int mt = 0; mt < 4; mt++) {
                mma_bf16(acc[mt][nt], ah[mt], bh);
                mma_bf16(acc[mt][nt], ah[mt], bl);
                mma_bf16(acc[mt][nt], al[mt], bh);
            }
        }
    };

    const int NC = K >> 4;
    ldgf(0); stsf(0);
    __syncthreads();
    for (int it = 1; it < NC; it++) {
        ldgf(it);
        compute((it - 1) & 1);
        stsf(it & 1);
        __syncthreads();
    }
    compute((NC - 1) & 1);

    // ---- epilogue ----
    if (TROUT) {
        // smem-transposed coalesced store: two 64-col groups, tile [64][132]
        float* ts = (float*)sm;
        const int batch = m0 >> 9;
        const int sr    = m0 & 511;
#pragma unroll
        for (int cg = 0; cg < 2; cg++) {
            __syncthreads();
            if (wc == cg) {
#pragma unroll
                for (int mt = 0; mt < 4; mt++) {
                    const int row0 = wr * 64 + mt * 16 + g;
                    const int row1 = row0 + 8;
#pragma unroll
                    for (int nt = 0; nt < 8; nt++) {
                        const int lc = nt * 8 + 2 * t;
                        ts[(lc    ) * 132 + row0] = acc[mt][nt][0];
                        ts[(lc + 1) * 132 + row0] = acc[mt][nt][1];
                        ts[(lc    ) * 132 + row1] = acc[mt][nt][2];
                        ts[(lc + 1) * 132 + row1] = acc[mt][nt][3];
                    }
                }
            }
            __syncthreads();
#pragma unroll
            for (int i = 0; i < 16; i++) {
                const int flat = tid + 128 * i;      // 0..2047
                const int lc = flat >> 5;            // col 0..63
                const int rq = (flat & 31) * 4;      // row quad
                float4 v = *(float4*)&ts[lc * 132 + rq];
                *(float4*)&C[((long)batch * N + n0 + cg * 64 + lc) * 512 + sr + rq] = v;
            }
        }
        return;
    }
#pragma unroll
    for (int mt = 0; mt < 4; mt++) {
        const int row0 = m0 + wr * 64 + mt * 16 + g;
        const int row1 = row0 + 8;
        float inv0 = 1.0f, inv1 = 1.0f;
        if (DENOM) {
            inv0 = 1.0f / denom[(long)zb * dstride + row0];
            inv1 = 1.0f / denom[(long)zb * dstride + row1];
        }
#pragma unroll
        for (int nt = 0; nt < 8; nt++) {
            const int col = n0 + wc * 64 + nt * 8 + 2 * t;
            float bv0 = 0.0f, bv1 = 0.0f;
            if (BIAS) { bv0 = bias[col]; bv1 = bias[col + 1]; }
            float v0 = acc[mt][nt][0] + bv0;
            float v1 = acc[mt][nt][1] + bv1;
            float v2 = acc[mt][nt][2] + bv0;
            float v3 = acc[mt][nt][3] + bv1;
            if (DENOM) { v0 *= inv0; v1 *= inv0; v2 *= inv1; v3 *= inv1; }
            if (RELU) {
                v0 = fmaxf(v0, 0.0f); v1 = fmaxf(v1, 0.0f);
                v2 = fmaxf(v2, 0.0f); v3 = fmaxf(v3, 0.0f);
            }
            *(float2*)&C[(long)row0 * N + col] = make_float2(v0, v1);
            *(float2*)&C[(long)row1 * N + col] = make_float2(v2, v3);
        }
    }
}

// ======= streaming softmax + head-mean: scores[B,H,S,S] -> adj, denom =======
__global__ __launch_bounds__(512, 1) void softmax_mean_kernel(
    const float* __restrict__ scores, const float* __restrict__ fmask,
    float* __restrict__ adj, float* __restrict__ denom)
{
    const int b   = blockIdx.y;
    const int r0  = blockIdx.x * 32;
    const int wid = threadIdx.x >> 5;
    const int lane = threadIdx.x & 31;
    const float rs = 0.10206207261596577f;   // 1/sqrt(96)

    float fmv[16];
#pragma unroll
    for (int c = 0; c < 4; c++) {
        float4 v = *(const float4*)&fmask[b * S_ + c * 128 + lane * 4];
        fmv[c*4+0] = v.x; fmv[c*4+1] = v.y; fmv[c*4+2] = v.z; fmv[c*4+3] = v.w;
    }

#pragma unroll
    for (int rr = 0; rr < 2; rr++) {
        const int i  = r0 + wid * 2 + rr;
        const float fr = fmask[b * S_ + i];
        float acc[16];
#pragma unroll
        for (int e = 0; e < 16; e++) acc[e] = 0.0f;

        for (int h = 0; h < H_; h++) {
            const float* p = scores + ((long)(b * H_ + h) * S_ + i) * S_;
            float ev[16];
#pragma unroll
            for (int c = 0; c < 4; c++) {
                float4 v = *(const float4*)&p[c * 128 + lane * 4];
                ev[c*4+0] = v.x; ev[c*4+1] = v.y; ev[c*4+2] = v.z; ev[c*4+3] = v.w;
            }
            float mx = -INFINITY;
#pragma unroll
            for (int e = 0; e < 16; e++) {
                float vv = (fr * fmv[e] == 0.0f) ? -1e9f : ev[e] * rs;
                ev[e] = vv;
                mx = fmaxf(mx, vv);
            }
            mx = fmaxf(mx, __shfl_xor_sync(0xffffffffu, mx, 1));
            mx = fmaxf(mx, __shfl_xor_sync(0xffffffffu, mx, 2));
            mx = fmaxf(mx, __shfl_xor_sync(0xffffffffu, mx, 4));
            mx = fmaxf(mx, __shfl_xor_sync(0xffffffffu, mx, 8));
            mx = fmaxf(mx, __shfl_xor_sync(0xffffffffu, mx, 16));
            float s = 0.0f;
#pragma unroll
            for (int e = 0; e < 16; e++) {
                float x = fast_exp(ev[e] - mx);
                ev[e] = x;
                s += x;
            }
            s += __shfl_xor_sync(0xffffffffu, s, 1);
            s += __shfl_xor_sync(0xffffffffu, s, 2);
            s += __shfl_xor_sync(0xffffffffu, s, 4);
            s += __shfl_xor_sync(0xffffffffu, s, 8);
            s += __shfl_xor_sync(0xffffffffu, s, 16);
            const float inv = 1.0f / (8.0f * s);
#pragma unroll
            for (int e = 0; e < 16; e++) acc[e] = fmaf(ev[e], inv, acc[e]);
        }

        float* arow = adj + ((long)b * S_ + i) * S_;
#pragma unroll
        for (int c = 0; c < 4; c++) {
            float4 o;
#pragma unroll
            for (int e = 0; e < 4; e++) {
                int j = c * 128 + lane * 4 + e;
                float v = acc[c * 4 + e];
                if (j == i) { denom[b * S_ + i] = 3.0f - v; v = 1.0f; }
                ((float*)&o)[e] = v;
            }
            *(float4*)&arow[c * 128 + lane * 4] = o;
        }
    }
}

// ---------------- small guarded SGEMM (FFN1 only: M=32) ----------------------
template<bool TRANSB, bool BIAS, bool RELU>
__global__ __launch_bounds__(256) void sgemm_small(
    const float* __restrict__ A, const float* __restrict__ Bm, float* __restrict__ C,
    int M, int N, int K, const float* __restrict__ bias)
{
    __shared__ float As[16][68];
    __shared__ float Bs[16][68];
    const int m0 = blockIdx.y * 64, n0 = blockIdx.x * 64;
    const int tid = threadIdx.x;
    const int tx = tid & 15, ty = tid >> 4;
    float acc[4][4];
#pragma unroll
    for (int i = 0; i < 4; i++)
#pragma unroll
        for (int j = 0; j < 4; j++) acc[i][j] = 0.0f;
    const int arow = tid >> 2, akq = (tid & 3) * 4;
    for (int k0 = 0; k0 < K; k0 += 16) {
        float4 av = make_float4(0.f,0.f,0.f,0.f);
        if (m0 + arow < M)
            av = *(const float4*)&A[(long)(m0 + arow) * K + k0 + akq];
        As[akq+0][arow]=av.x; As[akq+1][arow]=av.y;
        As[akq+2][arow]=av.z; As[akq+3][arow]=av.w;
        if (!TRANSB) {
            const int kr = tid >> 4, nq = (tid & 15) * 4;
            float4 bv = make_float4(0.f,0.f,0.f,0.f);
            if (n0 + nq < N)
                bv = *(const float4*)&Bm[(long)(k0+kr)*N + n0 + nq];
            Bs[kr][nq+0]=bv.x; Bs[kr][nq+1]=bv.y; Bs[kr][nq+2]=bv.z; Bs[kr][nq+3]=bv.w;
        } else {
            const int nrow = tid >> 2, kq = (tid & 3) * 4;
            float4 bv = make_float4(0.f,0.f,0.f,0.f);
            if (n0 + nrow < N)
                bv = *(const float4*)&Bm[(long)(n0+nrow)*K + k0 + kq];
            Bs[kq+0][nrow]=bv.x; Bs[kq+1][nrow]=bv.y; Bs[kq+2][nrow]=bv.z; Bs[kq+3][nrow]=bv.w;
        }
        __syncthreads();
#pragma unroll
        for (int kk = 0; kk < 16; kk++) {
            float4 a = *(const float4*)&As[kk][ty*4];
            float4 b = *(const float4*)&Bs[kk][tx*4];
            acc[0][0]=fmaf(a.x,b.x,acc[0][0]); acc[0][1]=fmaf(a.x,b.y,acc[0][1]);
            acc[0][2]=fmaf(a.x,b.z,acc[0][2]); acc[0][3]=fmaf(a.x,b.w,acc[0][3]);
            acc[1][0]=fmaf(a.y,b.x,acc[1][0]); acc[1][1]=fmaf(a.y,b.y,acc[1][1]);
            acc[1][2]=fmaf(a.y,b.z,acc[1][2]); acc[1][3]=fmaf(a.y,b.w,acc[1][3]);
            acc[2][0]=fmaf(a.z,b.x,acc[2][0]); acc[2][1]=fmaf(a.z,b.y,acc[2][1]);
            acc[2][2]=fmaf(a.z,b.z,acc[2][2]); acc[2][3]=fmaf(a.z,b.w,acc[2][3]);
            acc[3][0]=fmaf(a.w,b.x,acc[3][0]); acc[3][1]=fmaf(a.w,b.y,acc[3][1]);
            acc[3][2]=fmaf(a.w,b.z,acc[3][2]); acc[3][3]=fmaf(a.w,b.w,acc[3][3]);
        }
        __syncthreads();
    }
#pragma unroll
    for (int i = 0; i < 4; i++) {
        int m = m0 + ty*4 + i;
        if (m >= M) continue;
#pragma unroll
        for (int j = 0; j < 4; j++) {
            int n = n0 + tx*4 + j;
            if (n < N) {
                float v = acc[i][j];
                if (BIAS) v += bias[n];
                if (RELU) v = fmaxf(v, 0.0f);
                C[(long)m * N + n] = v;
            }
        }
    }
}

// ---------------- aspect max-pool ----------------
__global__ void pool_kernel(const float* __restrict__ tok,
                            const int* __restrict__ am,
                            float* __restrict__ pool)
{
    int d = blockIdx.x * 256 + threadIdx.x;
    int b = blockIdx.y;
    if (d >= D_) return;
    const float* tp = tok + (long)b * S_ * D_;
    const int*   ap = am + b * S_;
    float m = -10000.0f;
#pragma unroll 8
    for (int s = 0; s < S_; s++) {
        float v = (ap[s] == 1) ? tp[(long)s * D_ + d] : -10000.0f;
        m = fmaxf(m, v);
    }
    pool[b * D_ + d] = m;
}

// ---------------- FFN2 + output assembly ----------------
__global__ void ffn2_kernel(const float* __restrict__ h,
                            const float* __restrict__ w2,
                            const float* __restrict__ b2,
                            const float* __restrict__ pool,
                            float* __restrict__ out)
{
    int bid = blockIdx.x;
    if (bid < 96) {
        int idx = bid * 256 + threadIdx.x;
        out[B_ * C_ + idx] = pool[idx];
    } else {
        int t = threadIdx.x;
        if (t < B_ * C_) {
            int b = t / C_, c = t % C_;
            const float* hp = h + b * D_;
            const float* wp = w2 + c * D_;
            float s = b2[c];
            for (int d = 0; d < D_; d++) s = fmaf(hp[d], wp[d], s);
            out[b * C_ + c] = s;
        }
    }
}

// ---------------- orchestration ----------------
extern "C" void kernel_launch(void* const* d_in, const int* in_sizes, int n_in,
                              void* d_out, int out_size)
{
    const float* x     = (const float*)d_in[0];
    const float* fmask = (const float*)d_in[1];
    const int*   amask = (const int*)  d_in[2];
    const float* wq    = (const float*)d_in[3];
    const float* wk    = (const float*)d_in[4];
    const float* gw    = (const float*)d_in[5];
    const float* gb    = (const float*)d_in[6];
    const float* w1    = (const float*)d_in[7];
    const float* b1    = (const float*)d_in[8];
    const float* w2    = (const float*)d_in[9];
    const float* b2    = (const float*)d_in[10];
    float* out = (float*)d_out;

    float *pqk, *pwqk, *pscores, *padj, *pden, *pvt, *pt1, *pt2, *ppool, *phid;
    cudaGetSymbolAddress((void**)&pqk,    g_qk);
    cudaGetSymbolAddress((void**)&pwqk,   g_wqk);
    cudaGetSymbolAddress((void**)&pscores,g_scores);
    cudaGetSymbolAddress((void**)&padj,   g_adj);
    cudaGetSymbolAddress((void**)&pden,   g_den);
    cudaGetSymbolAddress((void**)&pvt,    g_vt);
    cudaGetSymbolAddress((void**)&pt1,    g_t1);
    cudaGetSymbolAddress((void**)&pt2,    g_t2);
    cudaGetSymbolAddress((void**)&ppool,  g_pool);
    cudaGetSymbolAddress((void**)&phid,   g_hid);

    cudaFuncSetAttribute(gemm_mma<false,false,false,false>,
                         cudaFuncAttributeMaxDynamicSharedMemorySize, MMA_SMEM);
    cudaFuncSetAttribute(gemm_mma<true,false,false,false>,
                         cudaFuncAttributeMaxDynamicSharedMemorySize, MMA_SMEM);
    cudaFuncSetAttribute(gemm_mma<false,true,true,true>,
                         cudaFuncAttributeMaxDynamicSharedMemorySize, MMA_SMEM);

    // 0) concat/transpose weights -> [1536][768] TRANSB layout
    wqk_transpose<<<(H_*D_*DK_ + 255) / 256, 256>>>(wq, wk, pwqk);

    // 1) v = x @ W0^T  (TROUT -> vT [b][768][512], coalesced via smem)
    gemm_mma<true,false,false,false><<<dim3(D_/128, (B_*S_)/128, 1), 128, MMA_SMEM>>>(
        x, gw, pvt, B_*S_, D_, D_, D_, D_,
        0L, 0L, 0L, 0L, 0L, 1, nullptr, nullptr, 0);

    // 2) fused Q|K projection: [16384x768] @ wqkT[1536x768]^T
    gemm_mma<false,false,false,false><<<dim3(QKW/128, (B_*S_)/128, 1), 128, MMA_SMEM>>>(
        x, pwqk, pqk, B_*S_, QKW, D_, D_, D_,
        0L, 0L, 0L, 0L, 0L, 1, nullptr, nullptr, 0);

    // 3) scores[b,h] = Q_bh @ K_bh^T  (batched, K=96)
    gemm_mma<false,false,false,false><<<dim3(4, 4, B_*H_), 128, MMA_SMEM>>>(
        pqk, pqk + D_, pscores, S_, S_, DK_, QKW, QKW,
        (long)S_*QKW, (long)DK_, (long)S_*QKW, (long)DK_, (long)S_*S_, H_,
        nullptr, nullptr, 0);

    // 4) streaming softmax + head-mean -> adj, denom
    softmax_mean_kernel<<<dim3(16, B_), 512>>>(pscores, fmask, padj, pden);

    // 5) GCN layer 1: t1 = relu((adj @ v + b0)/den)   (B = vT, TRANSB fast path)
    gemm_mma<false,true,true,true><<<dim3(D_/128, S_/128, B_), 128, MMA_SMEM>>>(
        padj, pvt, pt1, S_, D_, S_, S_, S_,
        (long)S_*S_, 0L, (long)D_*S_, 0L, (long)S_*D_, 1, gb, pden, S_);

    // 6) u = t1 @ W1^T  (TROUT -> uT in g_vt)
    gemm_mma<true,false,false,false><<<dim3(D_/128, (B_*S_)/128, 1), 128, MMA_SMEM>>>(
        pt1, gw + (long)D_*D_, pvt, B_*S_, D_, D_, D_, D_,
        0L, 0L, 0L, 0L, 0L, 1, nullptr, nullptr, 0);

    // 7) GCN layer 2: t2 = relu((adj @ u + b1)/den)
    gemm_mma<false,true,true,true><<<dim3(D_/128, S_/128, B_), 128, MMA_SMEM>>>(
        padj, pvt, pt2, S_, D_, S_, S_, S_,
        (long)S_*S_, 0L, (long)D_*S_, 0L, (long)S_*D_, 1, gb + D_, pden, S_);

    // 8) aspect max-pool -> preds
    pool_kernel<<<dim3(3, B_), 256>>>(pt2, amask, ppool);

    // 9) FFN1
    sgemm_small<true,true,true><<<dim3(12, 1, 1), 256>>>(
        ppool, w1, phid, B_, D_, D_, b1);

    // 10) FFN2 + output
    ffn2_kernel<<<97, 256>>>(phid, w2, b2, ppool, out);
}

// round 11
// speedup vs baseline: 1.1680x; 1.1680x over previous
#include <cuda_runtime.h>
#include <math.h>
#include <stdint.h>

#define B_  32
#define S_  512
#define D_  768
#define H_  8
#define DK_ 96
#define C_  3
#define QKW 1536   // fused q|k width

// ---------------- scratch (device globals; no allocs allowed) ----------------
__device__ float g_qk    [(long)B_*S_*QKW];
__device__ float g_wqk   [D_*QKW];
__device__ float g_scores[(long)B_*H_*S_*S_];   // 256 MiB
__device__ float g_adj   [(long)B_*S_*S_];
__device__ float g_den   [B_*S_];
__device__ float g_ax    [B_*S_*D_];
__device__ float g_t1    [B_*S_*D_];
__device__ float g_t2    [B_*S_*D_];
__device__ float g_pool  [B_*D_];
__device__ float g_hid   [B_*D_];

// ---------------- bf16x3 helpers ----------------
__device__ __forceinline__ void bsplit2(float x, float y, uint32_t& h, uint32_t& l) {
    uint32_t bx = __float_as_uint(x), by = __float_as_uint(y);
    h = __byte_perm(bx, by, 0x7632);          // {y_hi16, x_hi16}
    float lx = x - __uint_as_float(bx & 0xFFFF0000u);
    float ly = y - __uint_as_float(by & 0xFFFF0000u);
    asm("cvt.rn.bf16x2.f32 %0, %1, %2;" : "=r"(l) : "f"(ly), "f"(lx));
}
__device__ __forceinline__ void mma_bf16(float* c, const uint32_t* a, const uint32_t* b) {
    asm volatile(
        "mma.sync.aligned.m16n8k16.row.col.f32.bf16.bf16.f32 "
        "{%0,%1,%2,%3}, {%4,%5,%6,%7}, {%8,%9}, {%0,%1,%2,%3};"
        : "+f"(c[0]), "+f"(c[1]), "+f"(c[2]), "+f"(c[3])
        : "r"(a[0]), "r"(a[1]), "r"(a[2]), "r"(a[3]), "r"(b[0]), "r"(b[1]));
}
__device__ __forceinline__ void ldsm4(uint32_t& r0, uint32_t& r1,
                                      uint32_t& r2, uint32_t& r3, uint32_t addr) {
    asm volatile("ldmatrix.sync.aligned.m8n8.x4.shared.b16 {%0,%1,%2,%3}, [%4];"
                 : "=r"(r0), "=r"(r1), "=r"(r2), "=r"(r3) : "r"(addr));
}
__device__ __forceinline__ uint32_t smem_addr32(const void* p) {
    uint32_t a;
    asm("{ .reg .u64 t; cvta.to.shared.u64 t, %1; cvt.u32.u64 %0, t; }"
        : "=r"(a) : "l"(p));
    return a;
}

// ---------------- fast exp ----------------
__device__ __forceinline__ float fast_exp(float x) {
    float y = fmaxf(x * 1.4426950408889634f, -126.0f);
    float t = __fadd_rn(y, 12582912.0f);
    float n = __fsub_rn(t, 12582912.0f);
    float f = __fsub_rn(y, n);
    float p = 0.0013333558f;
    p = fmaf(p, f, 0.0096181291f);
    p = fmaf(p, f, 0.0555041087f);
    p = fmaf(p, f, 0.2402265070f);
    p = fmaf(p, f, 0.6931471806f);
    p = fmaf(p, f, 1.0f);
    int e = (int)n;
    return __int_as_float(__float_as_int(p) + (e << 23));
}

// ---------------- weight concat/transpose: [H,D,DK]x2 -> [D, q|k] (K,N) -----
__global__ void wqk_transpose(const float* __restrict__ wq,
                              const float* __restrict__ wk,
                              float* __restrict__ out)
{
    int idx = blockIdx.x * 256 + threadIdx.x;
    if (idx >= H_ * D_ * DK_) return;
    int h = idx / (D_ * DK_);
    int r = idx % (D_ * DK_);
    int d = r / DK_, j = r % DK_;
    out[(long)d * QKW + h * DK_ + j]       = wq[idx];
    out[(long)d * QKW + D_ + h * DK_ + j]  = wk[idx];
}

// ========= bf16x3 GEMM: 128x128 tile, 4 warps of 64x64, KC=16, ldmatrix =====
// TRANSB: B is [N,K] rows; else [K,N]. Two-level batch z = zb*hdiv + zh.
#define SRW 12
#define TSZ (128 * SRW)
#define MMA_SMEM (8 * TSZ * 4)          // 49152 B

template<bool TRANSB, bool BIAS, bool RELU, bool DENOM>
__global__ __launch_bounds__(128, 2) void gemm_mma(
    const float* __restrict__ A, const float* __restrict__ Bm, float* __restrict__ C,
    int M, int N, int K, int lda, int ldb,
    long sA, long hA, long sB, long hB, long sC, int hdiv,
    const float* __restrict__ bias, const float* __restrict__ denom, int dstride)
{
    extern __shared__ uint32_t sm[];

    const int tid  = threadIdx.x;
    const int wid  = tid >> 5;
    const int lane = tid & 31;
    const int t    = lane & 3;
    const int g    = lane >> 2;
    const int wr   = wid & 1;
    const int wc   = wid >> 1;

    const int z  = blockIdx.z;
    const int zb = z / hdiv;
    const int zh = z - zb * hdiv;
    A  += (long)zb * sA + (long)zh * hA;
    Bm += (long)zb * sB + (long)zh * hB;
    C  += (long)z * sC;

    const int m0 = blockIdx.y * 128;
    const int n0 = blockIdx.x * 128;

    // ldmatrix lane offsets (bytes, within a tile buffer)
    const int r8l = lane & 7;
    const uint32_t aoffA = (uint32_t)(((wr * 64 + ((lane >> 3) & 1) * 8 + r8l) * SRW
                                       + (lane >> 4) * 4) * 4);
    const uint32_t aoffB = (uint32_t)(((wc * 64 + (lane >> 4) * 8 + r8l) * SRW
                                       + ((lane >> 3) & 1) * 4) * 4);
    const uint32_t smaddr = smem_addr32(sm);

    float acc[4][8][4];
#pragma unroll
    for (int i = 0; i < 4; i++)
#pragma unroll
        for (int j = 0; j < 8; j++)
#pragma unroll
            for (int e = 0; e < 4; e++) acc[i][j][e] = 0.0f;

    float4 pa[4], pb[4];

    auto ldgf = [&](int c) {
        const float* ap = A + (long)(m0 + tid) * lda + c * 16;
#pragma unroll
        for (int i = 0; i < 4; i++) pa[i] = *(const float4*)(ap + i * 4);
        if (TRANSB) {
            const float* bp = Bm + (long)(n0 + tid) * ldb + c * 16;
#pragma unroll
            for (int i = 0; i < 4; i++) pb[i] = *(const float4*)(bp + i * 4);
        } else {
            const float* bp = Bm + (long)(c * 16) * ldb + n0 + tid;
#pragma unroll
            for (int i = 0; i < 4; i++) {
                pb[i].x = bp[(long)(4 * i + 0) * ldb];
                pb[i].y = bp[(long)(4 * i + 1) * ldb];
                pb[i].z = bp[(long)(4 * i + 2) * ldb];
                pb[i].w = bp[(long)(4 * i + 3) * ldb];
            }
        }
    };
    auto stsf = [&](int s) {
        uint32_t hw[8], lw[8];
#pragma unroll
        for (int i = 0; i < 4; i++) {
            bsplit2(pa[i].x, pa[i].y, hw[2*i],   lw[2*i]);
            bsplit2(pa[i].z, pa[i].w, hw[2*i+1], lw[2*i+1]);
        }
        uint32_t* dah = sm + s * TSZ + tid * SRW;
        uint32_t* dal = sm + (2 + s) * TSZ + tid * SRW;
        *(uint4*)(dah)     = make_uint4(hw[0], hw[1], hw[2], hw[3]);
        *(uint4*)(dah + 4) = make_uint4(hw[4], hw[5], hw[6], hw[7]);
        *(uint4*)(dal)     = make_uint4(lw[0], lw[1], lw[2], lw[3]);
        *(uint4*)(dal + 4) = make_uint4(lw[4], lw[5], lw[6], lw[7]);
#pragma unroll
        for (int i = 0; i < 4; i++) {
            bsplit2(pb[i].x, pb[i].y, hw[2*i],   lw[2*i]);
            bsplit2(pb[i].z, pb[i].w, hw[2*i+1], lw[2*i+1]);
        }
        uint32_t* dbh = sm + (4 + s) * TSZ + tid * SRW;
        uint32_t* dbl = sm + (6 + s) * TSZ + tid * SRW;
        *(uint4*)(dbh)     = make_uint4(hw[0], hw[1], hw[2], hw[3]);
        *(uint4*)(dbh + 4) = make_uint4(hw[4], hw[5], hw[6], hw[7]);
        *(uint4*)(dbl)     = make_uint4(lw[0], lw[1], lw[2], lw[3]);
        *(uint4*)(dbl + 4) = make_uint4(lw[4], lw[5], lw[6], lw[7]);
    };

    auto compute = [&](int s) {
        const uint32_t aHb = smaddr + (uint32_t)((s)     * TSZ * 4) + aoffA;
        const uint32_t aLb = smaddr + (uint32_t)((2 + s) * TSZ * 4) + aoffA;
        const uint32_t bHb = smaddr + (uint32_t)((4 + s) * TSZ * 4) + aoffB;
        const uint32_t bLb = smaddr + (uint32_t)((6 + s) * TSZ * 4) + aoffB;
        uint32_t ah[4][4], al[4][4];
#pragma unroll
        for (int mt = 0; mt < 4; mt++) {
            const uint32_t o = mt * (16 * SRW * 4);
            ldsm4(ah[mt][0], ah[mt][1], ah[mt][2], ah[mt][3], aHb + o);
            ldsm4(al[mt][0], al[mt][1], al[mt][2], al[mt][3], aLb + o);
        }
#pragma unroll
        for (int p = 0; p < 4; p++) {
            const uint32_t o = p * (16 * SRW * 4);
            uint32_t bh[4], bl[4];
            ldsm4(bh[0], bh[1], bh[2], bh[3], bHb + o);
            ldsm4(bl[0], bl[1], bl[2], bl[3], bLb + o);
#pragma unroll
            for (int mt = 0; mt < 4; mt++) {
                mma_bf16(acc[mt][2*p],     ah[mt], bh);
                mma_bf16(acc[mt][2*p],     ah[mt], bl);
                mma_bf16(acc[mt][2*p],     al[mt], bh);
                mma_bf16(acc[mt][2*p + 1], ah[mt], bh + 2);
                mma_bf16(acc[mt][2*p + 1], ah[mt], bl + 2);
                mma_bf16(acc[mt][2*p + 1], al[mt], bh + 2);
            }
        }
    };

    const int NC = K >> 4;
    ldgf(0); stsf(0);
    __syncthreads();
    for (int it = 1; it < NC; it++) {
        ldgf(it);
        compute((it - 1) & 1);
        stsf(it & 1);
        __syncthreads();
    }
    compute((NC - 1) & 1);

    // ---- epilogue ----
#pragma unroll
    for (int mt = 0; mt < 4; mt++) {
        const int row0 = m0 + wr * 64 + mt * 16 + g;
        const int row1 = row0 + 8;
        float inv0 = 1.0f, inv1 = 1.0f;
        if (DENOM) {
            inv0 = 1.0f / denom[(long)zb * dstride + row0];
            inv1 = 1.0f / denom[(long)zb * dstride + row1];
        }
#pragma unroll
        for (int nt = 0; nt < 8; nt++) {
            const int col = n0 + wc * 64 + nt * 8 + 2 * t;
            float bv0 = 0.0f, bv1 = 0.0f;
            if (BIAS) { bv0 = bias[col]; bv1 = bias[col + 1]; }
            float v0 = acc[mt][nt][0] + bv0;
            float v1 = acc[mt][nt][1] + bv1;
            float v2 = acc[mt][nt][2] + bv0;
            float v3 = acc[mt][nt][3] + bv1;
            if (DENOM) { v0 *= inv0; v1 *= inv0; v2 *= inv1; v3 *= inv1; }
            if (RELU) {
                v0 = fmaxf(v0, 0.0f); v1 = fmaxf(v1, 0.0f);
                v2 = fmaxf(v2, 0.0f); v3 = fmaxf(v3, 0.0f);
            }
            *(float2*)&C[(long)row0 * N + col] = make_float2(v0, v1);
            *(float2*)&C[(long)row1 * N + col] = make_float2(v2, v3);
        }
    }
}

// ======= streaming softmax + head-mean: scores[B,H,S,S] -> adj, denom =======
__global__ __launch_bounds__(512, 1) void softmax_mean_kernel(
    const float* __restrict__ scores, const float* __restrict__ fmask,
    float* __restrict__ adj, float* __restrict__ denom)
{
    const int b   = blockIdx.y;
    const int r0  = blockIdx.x * 32;
    const int wid = threadIdx.x >> 5;
    const int lane = threadIdx.x & 31;
    const float rs = 0.10206207261596577f;   // 1/sqrt(96)

    float fmv[16];
#pragma unroll
    for (int c = 0; c < 4; c++) {
        float4 v = *(const float4*)&fmask[b * S_ + c * 128 + lane * 4];
        fmv[c*4+0] = v.x; fmv[c*4+1] = v.y; fmv[c*4+2] = v.z; fmv[c*4+3] = v.w;
    }

#pragma unroll
    for (int rr = 0; rr < 2; rr++) {
        const int i  = r0 + wid * 2 + rr;
        const float fr = fmask[b * S_ + i];
        float acc[16];
#pragma unroll
        for (int e = 0; e < 16; e++) acc[e] = 0.0f;

        for (int h = 0; h < H_; h++) {
            const float* p = scores + ((long)(b * H_ + h) * S_ + i) * S_;
            float ev[16];
#pragma unroll
            for (int c = 0; c < 4; c++) {
                float4 v = *(const float4*)&p[c * 128 + lane * 4];
                ev[c*4+0] = v.x; ev[c*4+1] = v.y; ev[c*4+2] = v.z; ev[c*4+3] = v.w;
            }
            float mx = -INFINITY;
#pragma unroll
            for (int e = 0; e < 16; e++) {
                float vv = (fr * fmv[e] == 0.0f) ? -1e9f : ev[e] * rs;
                ev[e] = vv;
                mx = fmaxf(mx, vv);
            }
            mx = fmaxf(mx, __shfl_xor_sync(0xffffffffu, mx, 1));
            mx = fmaxf(mx, __shfl_xor_sync(0xffffffffu, mx, 2));
            mx = fmaxf(mx, __shfl_xor_sync(0xffffffffu, mx, 4));
            mx = fmaxf(mx, __shfl_xor_sync(0xffffffffu, mx, 8));
            mx = fmaxf(mx, __shfl_xor_sync(0xffffffffu, mx, 16));
            float s = 0.0f;
#pragma unroll
            for (int e = 0; e < 16; e++) {
                float x = fast_exp(ev[e] - mx);
                ev[e] = x;
                s += x;
            }
            s += __shfl_xor_sync(0xffffffffu, s, 1);
            s += __shfl_xor_sync(0xffffffffu, s, 2);
            s += __shfl_xor_sync(0xffffffffu, s, 4);
            s += __shfl_xor_sync(0xffffffffu, s, 8);
            s += __shfl_xor_sync(0xffffffffu, s, 16);
            const float inv = 1.0f / (8.0f * s);
#pragma unroll
            for (int e = 0; e < 16; e++) acc[e] = fmaf(ev[e], inv, acc[e]);
        }

        float* arow = adj + ((long)b * S_ + i) * S_;
#pragma unroll
        for (int c = 0; c < 4; c++) {
            float4 o;
#pragma unroll
            for (int e = 0; e < 4; e++) {
                int j = c * 128 + lane * 4 + e;
                float v = acc[c * 4 + e];
                if (j == i) { denom[b * S_ + i] = 3.0f - v; v = 1.0f; }
                ((float*)&o)[e] = v;
            }
            *(float4*)&arow[c * 128 + lane * 4] = o;
        }
    }
}

// ---------------- small guarded SGEMM (FFN1 only: M=32) ----------------------
template<bool TRANSB, bool BIAS, bool RELU>
__global__ __launch_bounds__(256) void sgemm_small(
    const float* __restrict__ A, const float* __restrict__ Bm, float* __restrict__ C,
    int M, int N, int K, const float* __restrict__ bias)
{
    __shared__ float As[16][68];
    __shared__ float Bs[16][68];
    const int m0 = blockIdx.y * 64, n0 = blockIdx.x * 64;
    const int tid = threadIdx.x;
    const int tx = tid & 15, ty = tid >> 4;
    float acc[4][4];
#pragma unroll
    for (int i = 0; i < 4; i++)
#pragma unroll
        for (int j = 0; j < 4; j++) acc[i][j] = 0.0f;
    const int arow = tid >> 2, akq = (tid & 3) * 4;
    for (int k0 = 0; k0 < K; k0 += 16) {
        float4 av = make_float4(0.f,0.f,0.f,0.f);
        if (m0 + arow < M)
            av = *(const float4*)&A[(long)(m0 + arow) * K + k0 + akq];
        As[akq+0][arow]=av.x; As[akq+1][arow]=av.y;
        As[akq+2][arow]=av.z; As[akq+3][arow]=av.w;
        if (!TRANSB) {
            const int kr = tid >> 4, nq = (tid & 15) * 4;
            float4 bv = make_float4(0.f,0.f,0.f,0.f);
            if (n0 + nq < N)
                bv = *(const float4*)&Bm[(long)(k0+kr)*N + n0 + nq];
            Bs[kr][nq+0]=bv.x; Bs[kr][nq+1]=bv.y; Bs[kr][nq+2]=bv.z; Bs[kr][nq+3]=bv.w;
        } else {
            const int nrow = tid >> 2, kq = (tid & 3) * 4;
            float4 bv = make_float4(0.f,0.f,0.f,0.f);
            if (n0 + nrow < N)
                bv = *(const float4*)&Bm[(long)(n0+nrow)*K + k0 + kq];
            Bs[kq+0][nrow]=bv.x; Bs[kq+1][nrow]=bv.y; Bs[kq+2][nrow]=bv.z; Bs[kq+3][nrow]=bv.w;
        }
        __syncthreads();
#pragma unroll
        for (int kk = 0; kk < 16; kk++) {
            float4 a = *(const float4*)&As[kk][ty*4];
            float4 b = *(const float4*)&Bs[kk][tx*4];
            acc[0][0]=fmaf(a.x,b.x,acc[0][0]); acc[0][1]=fmaf(a.x,b.y,acc[0][1]);
            acc[0][2]=fmaf(a.x,b.z,acc[0][2]); acc[0][3]=fmaf(a.x,b.w,acc[0][3]);
            acc[1][0]=fmaf(a.y,b.x,acc[1][0]); acc[1][1]=fmaf(a.y,b.y,acc[1][1]);
            acc[1][2]=fmaf(a.y,b.z,acc[1][2]); acc[1][3]=fmaf(a.y,b.w,acc[1][3]);
            acc[2][0]=fmaf(a.z,b.x,acc[2][0]); acc[2][1]=fmaf(a.z,b.y,acc[2][1]);
            acc[2][2]=fmaf(a.z,b.z,acc[2][2]); acc[2][3]=fmaf(a.z,b.w,acc[2][3]);
            acc[3][0]=fmaf(a.w,b.x,acc[3][0]); acc[3][1]=fmaf(a.w,b.y,acc[3][1]);
            acc[3][2]=fmaf(a.w,b.z,acc[3][2]); acc[3][3]=fmaf(a.w,b.w,acc[3][3]);
        }
        __syncthreads();
    }
#pragma unroll
    for (int i = 0; i < 4; i++) {
        int m = m0 + ty*4 + i;
        if (m >= M) continue;
#pragma unroll
        for (int j = 0; j < 4; j++) {
            int n = n0 + tx*4 + j;
            if (n < N) {
                float v = acc[i][j];
                if (BIAS) v += bias[n];
                if (RELU) v = fmaxf(v, 0.0f);
                C[(long)m * N + n] = v;
            }
        }
    }
}

// ---------------- aspect max-pool ----------------
__global__ void pool_kernel(const float* __restrict__ tok,
                            const int* __restrict__ am,
                            float* __restrict__ pool)
{
    int d = blockIdx.x * 256 + threadIdx.x;
    int b = blockIdx.y;
    if (d >= D_) return;
    const float* tp = tok + (long)b * S_ * D_;
    const int*   ap = am + b * S_;
    float m = -10000.0f;
#pragma unroll 8
    for (int s = 0; s < S_; s++) {
        float v = (ap[s] == 1) ? tp[(long)s * D_ + d] : -10000.0f;
        m = fmaxf(m, v);
    }
    pool[b * D_ + d] = m;
}

// ---------------- FFN2 + output assembly ----------------
__global__ void ffn2_kernel(const float* __restrict__ h,
                            const float* __restrict__ w2,
                            const float* __restrict__ b2,
                            const float* __restrict__ pool,
                            float* __restrict__ out)
{
    int bid = blockIdx.x;
    if (bid < 96) {
        int idx = bid * 256 + threadIdx.x;
        out[B_ * C_ + idx] = pool[idx];
    } else {
        int t = threadIdx.x;
        if (t < B_ * C_) {
            int b = t / C_, c = t % C_;
            const float* hp = h + b * D_;
            const float* wp = w2 + c * D_;
            float s = b2[c];
            for (int d = 0; d < D_; d++) s = fmaf(hp[d], wp[d], s);
            out[b * C_ + c] = s;
        }
    }
}

// ---------------- orchestration ----------------
extern "C" void kernel_launch(void* const* d_in, const int* in_sizes, int n_in,
                              void* d_out, int out_size)
{
    const float* x     = (const float*)d_in[0];
    const float* fmask = (const float*)d_in[1];
    const int*   amask = (const int*)  d_in[2];
    const float* wq    = (const float*)d_in[3];
    const float* wk    = (const float*)d_in[4];
    const float* gw    = (const float*)d_in[5];
    const float* gb    = (const float*)d_in[6];
    const float* w1    = (const float*)d_in[7];
    const float* b1    = (const float*)d_in[8];
    const float* w2    = (const float*)d_in[9];
    const float* b2    = (const float*)d_in[10];
    float* out = (float*)d_out;

    float *pqk, *pwqk, *pscores, *padj, *pden, *pax, *pt1, *pt2, *ppool, *phid;
    cudaGetSymbolAddress((void**)&pqk,    g_qk);
    cudaGetSymbolAddress((void**)&pwqk,   g_wqk);
    cudaGetSymbolAddress((void**)&pscores,g_scores);
    cudaGetSymbolAddress((void**)&padj,   g_adj);
    cudaGetSymbolAddress((void**)&pden,   g_den);
    cudaGetSymbolAddress((void**)&pax,    g_ax);
    cudaGetSymbolAddress((void**)&pt1,    g_t1);
    cudaGetSymbolAddress((void**)&pt2,    g_t2);
    cudaGetSymbolAddress((void**)&ppool,  g_pool);
    cudaGetSymbolAddress((void**)&phid,   g_hid);

    cudaFuncSetAttribute(gemm_mma<false,false,false,false>,
                         cudaFuncAttributeMaxDynamicSharedMemorySize, MMA_SMEM);
    cudaFuncSetAttribute(gemm_mma<true,false,false,false>,
                         cudaFuncAttributeMaxDynamicSharedMemorySize, MMA_SMEM);
    cudaFuncSetAttribute(gemm_mma<true,true,true,true>,
                         cudaFuncAttributeMaxDynamicSharedMemorySize, MMA_SMEM);

    // 0) concat/transpose weights -> [768][1536] (K,N)
    wqk_transpose<<<(H_*D_*DK_ + 255) / 256, 256>>>(wq, wk, pwqk);

    // 1) fused Q|K projection: [16384 x 768] @ [768 x 1536]
    gemm_mma<false,false,false,false><<<dim3(QKW/128, (B_*S_)/128, 1), 128, MMA_SMEM>>>(
        x, pwqk, pqk, B_*S_, QKW, D_, D_, QKW,
        0L, 0L, 0L, 0L, 0L, 1, nullptr, nullptr, 0);

    // 2a) scores[b,h] = Q_bh @ K_bh^T  (batched over z = b*8+h, K=96)
    gemm_mma<true,false,false,false><<<dim3(4, 4, B_*H_), 128, MMA_SMEM>>>(
        pqk, pqk + D_, pscores, S_, S_, DK_, QKW, QKW,
        (long)S_*QKW, (long)DK_, (long)S_*QKW, (long)DK_, (long)S_*S_, H_,
        nullptr, nullptr, 0);

    // 2b) streaming softmax + head-mean -> adj, denom
    softmax_mean_kernel<<<dim3(16, B_), 512>>>(pscores, fmask, padj, pden);

    // 3) GCN layers
    {
        dim3 g(D_/128, S_/128, B_);   // (6, 4, 32)
        gemm_mma<false,false,false,false><<<g, 128, MMA_SMEM>>>(
            padj, x, pax, S_, D_, S_, S_, D_,
            (long)S_*S_, 0L, (long)S_*D_, 0L, (long)S_*D_, 1, nullptr, nullptr, 0);
        gemm_mma<true,true,true,true><<<g, 128, MMA_SMEM>>>(
            pax, gw, pt1, S_, D_, D_, D_, D_,
            (long)S_*D_, 0L, 0L, 0L, (long)S_*D_, 1, gb, pden, S_);
        gemm_mma<false,false,false,false><<<g, 128, MMA_SMEM>>>(
            padj, pt1, pax, S_, D_, S_, S_, D_,
            (long)S_*S_, 0L, (long)S_*D_, 0L, (long)S_*D_, 1, nullptr, nullptr, 0);
        gemm_mma<true,true,true,true><<<g, 128, MMA_SMEM>>>(
            pax, gw + (long)D_*D_, pt2, S_, D_, D_, D_, D_,
            (long)S_*D_, 0L, 0L, 0L, (long)S_*D_, 1, gb + D_, pden, S_);
    }

    // 4) aspect max-pool -> preds
    pool_kernel<<<dim3(3, B_), 256>>>(pt2, amask, ppool);

    // 5) FFN1
    sgemm_small<true,true,true><<<dim3(12, 1, 1), 256>>>(
        ppool, w1, phid, B_, D_, D_, b1);

    // 6) FFN2 + output
    ffn2_kernel<<<97, 256>>>(phid, w2, b2, ppool, out);
}